// round 10
// baseline (speedup 1.0000x reference)
#include <cuda_runtime.h>
#include <cuda_fp16.h>
#include <math.h>
#include <stdint.h>

#define BATCH 128
#define SEQ   80
#define EMB_D 100
#define UNITS 1024
#define G4    4096
#define NBLK  128
#define KPAD  112

// ---------------- device scratch ----------------
__device__ __align__(16) float  g_XW1[(size_t)SEQ * BATCH * G4];
__device__ __align__(16) __half g_Eh[(size_t)SEQ * BATCH * KPAD];
__device__ __align__(16) __half g_W1h[(size_t)KPAD * G4];
__device__ __align__(16) __half g_B1h[(size_t)NBLK * UNITS * 64];   // [bx][k][U1(32)|W2(32)]
__device__ __align__(16) __half g_B2h[(size_t)NBLK * UNITS * 32];   // [bx][k][U2(32)]
__device__ __align__(16) __half g_h1[2][BATCH * UNITS];
__device__ __align__(16) __half g_h2[2][BATCH * UNITS];
__device__ float g_c1[BATCH * UNITS];
__device__ float g_c2[BATCH * UNITS];
__device__ unsigned g_cnt;
__device__ volatile unsigned g_gen;

__device__ __forceinline__ float sigf(float x) { return 1.0f / (1.0f + expf(-x)); }

// ---------------- PTX helpers ----------------
__device__ __forceinline__ unsigned smem_u32(const void* p) {
    return (unsigned)__cvta_generic_to_shared(p);
}
__device__ __forceinline__ void ldsm_x4(unsigned& r0, unsigned& r1, unsigned& r2, unsigned& r3,
                                        unsigned addr) {
    asm volatile("ldmatrix.sync.aligned.m8n8.x4.shared.b16 {%0,%1,%2,%3}, [%4];\n"
                 : "=r"(r0), "=r"(r1), "=r"(r2), "=r"(r3) : "r"(addr));
}
__device__ __forceinline__ void ldsm_x4t(unsigned& r0, unsigned& r1, unsigned& r2, unsigned& r3,
                                         unsigned addr) {
    asm volatile("ldmatrix.sync.aligned.m8n8.x4.trans.shared.b16 {%0,%1,%2,%3}, [%4];\n"
                 : "=r"(r0), "=r"(r1), "=r"(r2), "=r"(r3) : "r"(addr));
}
__device__ __forceinline__ void mma16816(float* d, const unsigned* a, unsigned b0, unsigned b1) {
    asm volatile(
        "mma.sync.aligned.m16n8k16.row.col.f32.f16.f16.f32 "
        "{%0,%1,%2,%3},{%4,%5,%6,%7},{%8,%9},{%0,%1,%2,%3};\n"
        : "+f"(d[0]), "+f"(d[1]), "+f"(d[2]), "+f"(d[3])
        : "r"(a[0]), "r"(a[1]), "r"(a[2]), "r"(a[3]), "r"(b0), "r"(b1));
}
__device__ __forceinline__ void cpa16(unsigned dst, const void* src) {
    asm volatile("cp.async.cg.shared.global [%0], [%1], 16;\n" :: "r"(dst), "l"(src));
}
__device__ __forceinline__ void cp_commit() { asm volatile("cp.async.commit_group;\n"); }
__device__ __forceinline__ void cp_waitn(int n) {
    if (n == 0) asm volatile("cp.async.wait_group 0;\n");
    else if (n == 1) asm volatile("cp.async.wait_group 1;\n");
    else asm volatile("cp.async.wait_group 2;\n");
}

// ---------------- init (deterministic per replay) ----------------
__global__ void init_kernel() {
    int i = blockIdx.x * blockDim.x + threadIdx.x;
    if (i == 0) { g_cnt = 0; g_gen = 0; }
    if (i < BATCH * UNITS) {
        g_h1[0][i] = __float2half(0.f); g_h1[1][i] = __float2half(0.f);
        g_h2[0][i] = __float2half(0.f); g_h2[1][i] = __float2half(0.f);
        g_c1[i] = 0.f; g_c2[i] = 0.f;
    }
}

// ---------------- gather embedding rows -> fp16 [m][112] ----------------
__global__ void gather_emb(const int* __restrict__ x, const float* __restrict__ emb) {
    int m = blockIdx.x;
    int tid = threadIdx.x;
    int b = m & 127, t = m >> 7;
    int tok = x[b * SEQ + t];
    if (tid < KPAD)
        g_Eh[(size_t)m * KPAD + tid] =
            __float2half(tid < EMB_D ? emb[(size_t)tok * EMB_D + tid] : 0.f);
}

__global__ void pack_w1(const float* __restrict__ W1) {
    int k = blockIdx.x;
    for (int n = threadIdx.x; n < G4; n += blockDim.x)
        g_W1h[(size_t)k * G4 + n] = __float2half(k < EMB_D ? W1[(size_t)k * G4 + n] : 0.f);
}

// ---------------- pack recurrent weights into per-block fp16 slices ----------------
__global__ void pack_b(const float* __restrict__ U1, const float* __restrict__ W2,
                       const float* __restrict__ U2) {
    const size_t tot1 = (size_t)NBLK * UNITS * 64;
    for (size_t i = blockIdx.x * (size_t)blockDim.x + threadIdx.x; i < tot1;
         i += (size_t)gridDim.x * blockDim.x) {
        int c  = (int)(i & 63);
        int k  = (int)((i >> 6) & 1023);
        int bx = (int)(i >> 16);
        int cc = c & 31;
        size_t src = (size_t)k * G4 + (cc >> 3) * UNITS + bx * 8 + (cc & 7);
        g_B1h[i] = __float2half(c < 32 ? U1[src] : W2[src]);
    }
    const size_t tot2 = (size_t)NBLK * UNITS * 32;
    for (size_t i = blockIdx.x * (size_t)blockDim.x + threadIdx.x; i < tot2;
         i += (size_t)gridDim.x * blockDim.x) {
        int c  = (int)(i & 31);
        int k  = (int)((i >> 5) & 1023);
        int bx = (int)(i >> 15);
        size_t src = (size_t)k * G4 + (c >> 3) * UNITS + bx * 8 + (c & 7);
        g_B2h[i] = __float2half(U2[src]);
    }
}

// ---------------- XW1 = Eh @ W1h + b1 (mma.sync; verified) ----------------
__global__ void __launch_bounds__(256) xw1_mma(const float* __restrict__ b1,
                                               float* __restrict__ XW1) {
    __shared__ __align__(16) __half sA[128 * 120];
    __shared__ __align__(16) __half sB[112 * 72];
    const int n0 = blockIdx.x * 64, m0 = blockIdx.y * 128;
    const int tid = threadIdx.x, lane = tid & 31, w = tid >> 5;
    const int wm = w >> 1, wn = w & 1;
    {
        int r = tid >> 1, part = tid & 1;
        const uint4* src = (const uint4*)(g_Eh + (size_t)(m0 + r) * KPAD + part * 56);
        uint4* dst = (uint4*)(sA + r * 120 + part * 56);
#pragma unroll
        for (int j = 0; j < 7; ++j) dst[j] = src[j];
    }
#pragma unroll
    for (int j = 0; j < 4; ++j) {
        int idx = tid + j * 256;
        if (idx < 896) {
            int k = idx >> 3, c = idx & 7;
            *(uint4*)(sB + k * 72 + c * 8) = *(const uint4*)(g_W1h + (size_t)k * G4 + n0 + c * 8);
        }
    }
    __syncthreads();
    float acc[2][4][4];
#pragma unroll
    for (int a = 0; a < 2; ++a)
#pragma unroll
        for (int b = 0; b < 4; ++b)
#pragma unroll
            for (int i = 0; i < 4; ++i) acc[a][b][i] = 0.f;
#pragma unroll
    for (int ks = 0; ks < 7; ++ks) {
        unsigned a0[4], a1r[4], bA[4], bB[4];
        unsigned ar = smem_u32(sA) + (wm * 32 + (lane & 15)) * 240 + ks * 32 + (lane >> 4) * 16;
        ldsm_x4(a0[0], a0[1], a0[2], a0[3], ar);
        ldsm_x4(a1r[0], a1r[1], a1r[2], a1r[3], ar + 16 * 240);
        unsigned br = smem_u32(sB) + (ks * 16 + (lane & 15)) * 144 + wn * 64 + (lane >> 4) * 16;
        ldsm_x4t(bA[0], bA[1], bA[2], bA[3], br);
        ldsm_x4t(bB[0], bB[1], bB[2], bB[3], br + 32);
        mma16816(acc[0][0], a0, bA[0], bA[1]);
        mma16816(acc[0][1], a0, bA[2], bA[3]);
        mma16816(acc[0][2], a0, bB[0], bB[1]);
        mma16816(acc[0][3], a0, bB[2], bB[3]);
        mma16816(acc[1][0], a1r, bA[0], bA[1]);
        mma16816(acc[1][1], a1r, bA[2], bA[3]);
        mma16816(acc[1][2], a1r, bB[0], bB[1]);
        mma16816(acc[1][3], a1r, bB[2], bB[3]);
    }
#pragma unroll
    for (int mt = 0; mt < 2; ++mt)
#pragma unroll
        for (int nt = 0; nt < 4; ++nt)
#pragma unroll
            for (int i = 0; i < 4; ++i) {
                int rr = m0 + wm * 32 + mt * 16 + (lane >> 2) + (i >> 1) * 8;
                int cc = n0 + wn * 32 + nt * 8 + (lane & 3) * 2 + (i & 1);
                XW1[(size_t)rr * G4 + cc] = acc[mt][nt][i] + b1[cc];
            }
}

// ---------------- grid barrier: atomic arrive, plain-load poll ----------------
__device__ __forceinline__ void grid_barrier(unsigned phase) {
    __threadfence();
    __syncthreads();
    if (threadIdx.x == 0) {
        unsigned old = atomicAdd(&g_cnt, 1u);
        if (old == NBLK - 1) {
            g_cnt = 0;
            __threadfence();
            g_gen = phase;
        } else {
            while (g_gen < phase) __nanosleep(20);
        }
    }
    __syncthreads();
    __threadfence();
}

// stage layout (bytes): A1[128x72h]=18432 | A2=18432 | B1[64x72h]=9216 | B2[64x40h]=5120
#define O_A2 18432
#define O_B1 36864
#define O_B2 46080
#define STAGE 51200
// after 3 stages: zbC [128][36]f, zsW [128][36]f, zsU [128][36]f
#define O_ZB  (3 * STAGE)
#define O_ZSW (O_ZB + 18432)
#define O_ZSU (O_ZSW + 18432)
#define DYN_TOTAL (O_ZSU + 18432 + 1024)

__device__ __forceinline__ void issue_A(unsigned sb, const __half* A1, const __half* A2,
                                        int koff, int tid) {
#pragma unroll
    for (int j = 0; j < 4; ++j) {           // A1: 128x64 halves
        int idx = tid + j * 256; int r = idx >> 3, c = idx & 7;
        cpa16(sb + r * 144 + c * 16, A1 + r * UNITS + koff + c * 8);
    }
#pragma unroll
    for (int j = 0; j < 4; ++j) {           // A2
        int idx = tid + j * 256; int r = idx >> 3, c = idx & 7;
        cpa16(sb + O_A2 + r * 144 + c * 16, A2 + r * UNITS + koff + c * 8);
    }
}

__device__ __forceinline__ void issue_B(unsigned sb, const __half* B1p, const __half* B2p,
                                        int koff, int tid) {
#pragma unroll
    for (int j = 0; j < 2; ++j) {           // B1: 64x64 halves
        int idx = tid + j * 256; int k = idx >> 3, c = idx & 7;
        cpa16(sb + O_B1 + k * 144 + c * 16, B1p + (size_t)(koff + k) * 64 + c * 8);
    }
    {                                        // B2: 64x32 halves
        int k = tid >> 2, c = tid & 3;
        cpa16(sb + O_B2 + k * 80 + c * 16, B2p + (size_t)(koff + k) * 32 + c * 8);
    }
}

// warps 0-3: acc1 = h1 @ [U1|W2]  (tile 64x32, grid 2x2)
// warps 4-7: acc2 = h2 @ U2       (tile 64x16, grid 2x2)
__device__ __forceinline__ void compute_chunk(unsigned ab, float* acc, int wid, int lane) {
    if (wid < 4) {
        const int wm = wid >> 1, wn = wid & 1;
#pragma unroll
        for (int ks = 0; ks < 4; ++ks) {
            unsigned a[4][4], b0[4], b1[4];
            unsigned arow = ab + (wm * 64 + (lane & 15)) * 144 + ks * 32 + (lane >> 4) * 16;
#pragma unroll
            for (int mf = 0; mf < 4; ++mf)
                ldsm_x4(a[mf][0], a[mf][1], a[mf][2], a[mf][3], arow + mf * 16 * 144);
            unsigned brow = ab + O_B1 + (ks * 16 + (lane & 15)) * 144 + wn * 64 + (lane >> 4) * 16;
            ldsm_x4t(b0[0], b0[1], b0[2], b0[3], brow);
            ldsm_x4t(b1[0], b1[1], b1[2], b1[3], brow + 32);
#pragma unroll
            for (int mf = 0; mf < 4; ++mf) {
                mma16816(acc + (mf * 4 + 0) * 4, a[mf], b0[0], b0[1]);
                mma16816(acc + (mf * 4 + 1) * 4, a[mf], b0[2], b0[3]);
                mma16816(acc + (mf * 4 + 2) * 4, a[mf], b1[0], b1[1]);
                mma16816(acc + (mf * 4 + 3) * 4, a[mf], b1[2], b1[3]);
            }
        }
    } else {
        const int wm = (wid - 4) >> 1, wn = (wid - 4) & 1;
#pragma unroll
        for (int ks = 0; ks < 4; ++ks) {
            unsigned a[4][4], b0[4];
            unsigned arow = ab + O_A2 + (wm * 64 + (lane & 15)) * 144 + ks * 32 + (lane >> 4) * 16;
#pragma unroll
            for (int mf = 0; mf < 4; ++mf)
                ldsm_x4(a[mf][0], a[mf][1], a[mf][2], a[mf][3], arow + mf * 16 * 144);
            unsigned brow = ab + O_B2 + (ks * 16 + (lane & 15)) * 80 + wn * 32 + (lane >> 4) * 16;
            ldsm_x4t(b0[0], b0[1], b0[2], b0[3], brow);
#pragma unroll
            for (int mf = 0; mf < 4; ++mf) {
                mma16816(acc + (mf * 2 + 0) * 4, a[mf], b0[0], b0[1]);
                mma16816(acc + (mf * 2 + 1) * 4, a[mf], b0[2], b0[3]);
            }
        }
    }
}

// ---------------- persistent fused 2-layer recurrence, 81 ticks ----------------
extern __shared__ __align__(16) char dynsm_raw[];
__global__ void __launch_bounds__(256, 1) lstm_persist(const float* __restrict__ b2) {
    char* smem = (char*)(((uintptr_t)dynsm_raw + 1023) & ~(uintptr_t)1023);
    const int tid = threadIdx.x, lane = tid & 31, wid = tid >> 5;
    const int bx = blockIdx.x, u0 = bx * 8;
    const __half* B1p = g_B1h + (size_t)bx * UNITS * 64;
    const __half* B2p = g_B2h + (size_t)bx * UNITS * 32;
    unsigned st[3] = { smem_u32(smem), smem_u32(smem + STAGE), smem_u32(smem + 2 * STAGE) };
    float* zbS = (float*)(smem + O_ZB);     // [128][36] XW1 slice (gate-major cols)
    float* zsW = (float*)(smem + O_ZSW);    // [128][36] W2-part of z2
    float* zsU = (float*)(smem + O_ZSU);    // [128][36] U2-part of z2
    unsigned zbA = smem_u32(zbS);

    __shared__ float sb2[32];
    if (tid < 32) sb2[tid] = b2[(size_t)(tid >> 3) * UNITS + u0 + (tid & 7)];
    __syncthreads();

    // pre-loop: B tiles for chunks 0..2 of tick 0
    issue_B(st[0], B1p, B2p, 0, tid);
    issue_B(st[1], B1p, B2p, 64, tid);
    issue_B(st[2], B1p, B2p, 128, tid);
    cp_commit();

    for (int s = 0; s <= SEQ; ++s) {
        const __half* A1 = g_h1[(s & 1) ^ 1];
        const __half* A2 = g_h2[s & 1];
        __half* h1w = g_h1[s & 1];
        __half* h2w = g_h2[(s & 1) ^ 1];

        float acc[64];
#pragma unroll
        for (int i = 0; i < 64; ++i) acc[i] = 0.f;

        // group A0 (+ XW1 gate-bias slice for this tick)
        issue_A(st[0], A1, A2, 0, tid);
        if (s < SEQ) {
            const float* xw = g_XW1 + (size_t)s * BATCH * G4;
#pragma unroll
            for (int q = 0; q < 4; ++q) {
                int e = tid + q * 256;           // 0..1023
                int r = e >> 3, g = (e >> 1) & 3, hf = e & 1;
                cpa16(zbA + (r * 36 + g * 8 + hf * 4) * 4,
                      xw + (size_t)r * G4 + g * UNITS + u0 + hf * 4);
            }
        }
        cp_commit();
        issue_A(st[1], A1, A2, 64, tid);
        cp_commit();

        for (int kc = 0; kc < 16; ++kc) {
            if (kc == 0) {
                issue_A(st[2], A1, A2, 128, tid);   // B for chunk 2 was prefetched
                cp_commit();
            } else if (kc + 2 < 16) {
                unsigned sb = st[(kc + 2) % 3];
                issue_A(sb, A1, A2, (kc + 2) * 64, tid);
                issue_B(sb, B1p, B2p, (kc + 2) * 64, tid);
                cp_commit();
            }
            cp_waitn(kc <= 13 ? 2 : 15 - kc);
            __syncthreads();
            compute_chunk(st[kc % 3], acc, wid, lane);
            __syncthreads();
        }

        // prefetch next tick's B tiles (stages are free now; zs* is separate memory)
        if (s < SEQ) {
            issue_B(st[0], B1p, B2p, 0, tid);
            issue_B(st[1], B1p, B2p, 64, tid);
            issue_B(st[2], B1p, B2p, 128, tid);
            cp_commit();
        }

        // epilogue
        if (wid < 4) {
            const int wm = wid >> 1, wn = wid & 1;
            if (wn == 1) {
                // spill W2-part of z2 into zsW
#pragma unroll
                for (int mf = 0; mf < 4; ++mf)
#pragma unroll
                    for (int nf = 0; nf < 4; ++nf)
#pragma unroll
                        for (int i = 0; i < 4; ++i) {
                            int r = wm * 64 + mf * 16 + (lane >> 2) + (i >> 1) * 8;
                            int c = nf * 8 + (lane & 3) * 2 + (i & 1);
                            zsW[r * 36 + c] = acc[(mf * 4 + nf) * 4 + i];
                        }
            } else if (s < SEQ) {
                // layer-1 gates fully in-register (cols of acc == gates)
#pragma unroll
                for (int mf = 0; mf < 4; ++mf)
#pragma unroll
                    for (int rh = 0; rh < 2; ++rh) {
                        int r = wm * 64 + mf * 16 + (lane >> 2) + rh * 8;
#pragma unroll
                        for (int j = 0; j < 2; ++j) {
                            int ul = (lane & 3) * 2 + j;
                            float zi = acc[(mf * 4 + 0) * 4 + rh * 2 + j] + zbS[r * 36 + ul];
                            float zf = acc[(mf * 4 + 1) * 4 + rh * 2 + j] + zbS[r * 36 + 8 + ul];
                            float zg = acc[(mf * 4 + 2) * 4 + rh * 2 + j] + zbS[r * 36 + 16 + ul];
                            float zo = acc[(mf * 4 + 3) * 4 + rh * 2 + j] + zbS[r * 36 + 24 + ul];
                            int idx = r * UNITS + u0 + ul;
                            float c = sigf(zf) * g_c1[idx] + sigf(zi) * tanhf(zg);
                            g_c1[idx] = c;
                            h1w[idx] = __float2half(sigf(zo) * tanhf(c));
                        }
                    }
            }
        } else {
            // spill U2-part of z2 into zsU
            const int wm = (wid - 4) >> 1, wn = (wid - 4) & 1;
#pragma unroll
            for (int mf = 0; mf < 4; ++mf)
#pragma unroll
                for (int nf = 0; nf < 2; ++nf)
#pragma unroll
                    for (int i = 0; i < 4; ++i) {
                        int r = wm * 64 + mf * 16 + (lane >> 2) + (i >> 1) * 8;
                        int c = wn * 16 + nf * 8 + (lane & 3) * 2 + (i & 1);
                        zsU[r * 36 + c] = acc[(mf * 2 + nf) * 4 + i];
                    }
        }
        __syncthreads();

        // layer-2 gates: all 256 threads, 2 per batch row
        if (s > 0) {
            const int r = tid >> 1;
            const int j4 = (tid & 1) * 4;
#pragma unroll
            for (int j = 0; j < 4; ++j) {
                int ul = j4 + j;
                float zi = zsW[r * 36 + ul]      + zsU[r * 36 + ul]      + sb2[ul];
                float zf = zsW[r * 36 + 8 + ul]  + zsU[r * 36 + 8 + ul]  + sb2[8 + ul];
                float zg = zsW[r * 36 + 16 + ul] + zsU[r * 36 + 16 + ul] + sb2[16 + ul];
                float zo = zsW[r * 36 + 24 + ul] + zsU[r * 36 + 24 + ul] + sb2[24 + ul];
                int idx = r * UNITS + u0 + ul;
                float c = sigf(zf) * g_c2[idx] + sigf(zi) * tanhf(zg);
                g_c2[idx] = c;
                h2w[idx] = __float2half(sigf(zo) * tanhf(c));
            }
        }
        grid_barrier((unsigned)(s + 1));
    }
}

// ---------------- final dense + sigmoid ----------------
__global__ void final_kernel(const float* __restrict__ Wfc, const float* __restrict__ bfc,
                             float* __restrict__ out) {
    const int b = blockIdx.x;
    const int tid = threadIdx.x;
    const __half* h2 = g_h2[1];    // h2[79] written at tick 80 -> buffer (80&1)^1 = 1
    float s = 0.f;
#pragma unroll
    for (int k = 0; k < 8; ++k) {
        int u = tid + k * 128;
        s += __half2float(h2[b * UNITS + u]) * Wfc[u];
    }
#pragma unroll
    for (int o = 16; o > 0; o >>= 1) s += __shfl_down_sync(0xffffffffu, s, o);
    __shared__ float ws[4];
    if ((tid & 31) == 0) ws[tid >> 5] = s;
    __syncthreads();
    if (tid == 0) {
        float tot = ws[0] + ws[1] + ws[2] + ws[3] + bfc[0];
        out[b] = 1.0f / (1.0f + expf(-tot));
    }
}

// ---------------- launcher ----------------
extern "C" void kernel_launch(void* const* d_in, const int* in_sizes, int n_in,
                              void* d_out, int out_size) {
    const int*   x   = (const int*)d_in[0];
    const float* emb = (const float*)d_in[1];
    const float* W1  = (const float*)d_in[2];
    const float* U1  = (const float*)d_in[3];
    const float* b1  = (const float*)d_in[4];
    const float* W2  = (const float*)d_in[5];
    const float* U2  = (const float*)d_in[6];
    const float* b2  = (const float*)d_in[7];
    const float* Wfc = (const float*)d_in[8];
    const float* bfc = (const float*)d_in[9];
    float* out = (float*)d_out;

    float* XW1p;
    cudaGetSymbolAddress((void**)&XW1p, g_XW1);

    cudaFuncSetAttribute((const void*)lstm_persist,
                         cudaFuncAttributeMaxDynamicSharedMemorySize, DYN_TOTAL);

    init_kernel<<<512, 256>>>();
    gather_emb<<<SEQ * BATCH, 128>>>(x, emb);
    pack_w1<<<KPAD, 256>>>(W1);
    pack_b<<<2048, 256>>>(U1, W2, U2);
    xw1_mma<<<dim3(G4 / 64, SEQ * BATCH / 128), 256>>>(b1, XW1p);
    lstm_persist<<<NBLK, 256, DYN_TOTAL>>>(b2);
    final_kernel<<<BATCH, 128>>>(Wfc, bfc, out);
}

// round 11
// speedup vs baseline: 1.3437x; 1.3437x over previous
#include <cuda_runtime.h>
#include <cuda_fp16.h>
#include <math.h>
#include <stdint.h>

#define BATCH 128
#define SEQ   80
#define EMB_D 100
#define UNITS 1024
#define G4    4096
#define NBLK  128
#define KPAD  112

// ---------------- device scratch ----------------
__device__ __align__(16) float  g_XW1[(size_t)SEQ * BATCH * G4];
__device__ __align__(16) __half g_Eh[(size_t)SEQ * BATCH * KPAD];   // gathered emb, K padded
__device__ __align__(16) __half g_W1h[(size_t)KPAD * G4];
__device__ __align__(16) __half g_B1h[(size_t)NBLK * UNITS * 64];   // [bx][k][ U1(32) | W2(32) ]
__device__ __align__(16) __half g_B2h[(size_t)NBLK * UNITS * 32];   // [bx][k][ U2(32) ]
__device__ __align__(16) __half g_h1[2][BATCH * UNITS];
__device__ __align__(16) __half g_h2[2][BATCH * UNITS];
__device__ unsigned g_cnt;
__device__ unsigned g_gen;

__device__ __forceinline__ float sigf(float x) { return 1.0f / (1.0f + expf(-x)); }

// ---------------- PTX helpers ----------------
__device__ __forceinline__ unsigned smem_u32(const void* p) {
    return (unsigned)__cvta_generic_to_shared(p);
}
__device__ __forceinline__ void ldsm_x4(unsigned& r0, unsigned& r1, unsigned& r2, unsigned& r3,
                                        unsigned addr) {
    asm volatile("ldmatrix.sync.aligned.m8n8.x4.shared.b16 {%0,%1,%2,%3}, [%4];\n"
                 : "=r"(r0), "=r"(r1), "=r"(r2), "=r"(r3) : "r"(addr));
}
__device__ __forceinline__ void ldsm_x4t(unsigned& r0, unsigned& r1, unsigned& r2, unsigned& r3,
                                         unsigned addr) {
    asm volatile("ldmatrix.sync.aligned.m8n8.x4.trans.shared.b16 {%0,%1,%2,%3}, [%4];\n"
                 : "=r"(r0), "=r"(r1), "=r"(r2), "=r"(r3) : "r"(addr));
}
__device__ __forceinline__ void mma16816(float* d, const unsigned* a, unsigned b0, unsigned b1) {
    asm volatile(
        "mma.sync.aligned.m16n8k16.row.col.f32.f16.f16.f32 "
        "{%0,%1,%2,%3},{%4,%5,%6,%7},{%8,%9},{%0,%1,%2,%3};\n"
        : "+f"(d[0]), "+f"(d[1]), "+f"(d[2]), "+f"(d[3])
        : "r"(a[0]), "r"(a[1]), "r"(a[2]), "r"(a[3]), "r"(b0), "r"(b1));
}
__device__ __forceinline__ void cpa16(unsigned dst, const void* src) {
    asm volatile("cp.async.cg.shared.global [%0], [%1], 16;\n" :: "r"(dst), "l"(src));
}
__device__ __forceinline__ void cp_commit() { asm volatile("cp.async.commit_group;\n"); }
__device__ __forceinline__ void cp_wait1() { asm volatile("cp.async.wait_group 1;\n"); }
__device__ __forceinline__ void cp_wait0() { asm volatile("cp.async.wait_group 0;\n"); }

// ---------------- init (deterministic per replay) ----------------
__global__ void init_kernel() {
    int i = blockIdx.x * blockDim.x + threadIdx.x;
    if (i == 0) { g_cnt = 0; g_gen = 0; }
    if (i < BATCH * UNITS) {
        g_h1[0][i] = __float2half(0.f); g_h1[1][i] = __float2half(0.f);
        g_h2[0][i] = __float2half(0.f); g_h2[1][i] = __float2half(0.f);
    }
}

// ---------------- gather embedding rows -> fp16 [m][112] ----------------
__global__ void gather_emb(const int* __restrict__ x, const float* __restrict__ emb) {
    int m = blockIdx.x;                 // m = t*128 + b
    int tid = threadIdx.x;              // 128
    int b = m & 127, t = m >> 7;
    int tok = x[b * SEQ + t];
    if (tid < KPAD)
        g_Eh[(size_t)m * KPAD + tid] =
            __float2half(tid < EMB_D ? emb[(size_t)tok * EMB_D + tid] : 0.f);
}

__global__ void pack_w1(const float* __restrict__ W1) {
    int k = blockIdx.x;                 // 0..111
    for (int n = threadIdx.x; n < G4; n += blockDim.x)
        g_W1h[(size_t)k * G4 + n] = __float2half(k < EMB_D ? W1[(size_t)k * G4 + n] : 0.f);
}

// ---------------- pack recurrent weights into per-block fp16 slices ----------------
__global__ void pack_b(const float* __restrict__ U1, const float* __restrict__ W2,
                       const float* __restrict__ U2) {
    const size_t tot1 = (size_t)NBLK * UNITS * 64;
    for (size_t i = blockIdx.x * (size_t)blockDim.x + threadIdx.x; i < tot1;
         i += (size_t)gridDim.x * blockDim.x) {
        int c  = (int)(i & 63);
        int k  = (int)((i >> 6) & 1023);
        int bx = (int)(i >> 16);
        int cc = c & 31;
        size_t src = (size_t)k * G4 + (cc >> 3) * UNITS + bx * 8 + (cc & 7);
        g_B1h[i] = __float2half(c < 32 ? U1[src] : W2[src]);
    }
    const size_t tot2 = (size_t)NBLK * UNITS * 32;
    for (size_t i = blockIdx.x * (size_t)blockDim.x + threadIdx.x; i < tot2;
         i += (size_t)gridDim.x * blockDim.x) {
        int c  = (int)(i & 31);
        int k  = (int)((i >> 5) & 1023);
        int bx = (int)(i >> 15);
        size_t src = (size_t)k * G4 + (c >> 3) * UNITS + bx * 8 + (c & 7);
        g_B2h[i] = __float2half(U2[src]);
    }
}

// ---------------- XW1 = Eh @ W1h + b1 (tensor cores, K=112) ----------------
__global__ void __launch_bounds__(256) xw1_mma(const float* __restrict__ b1,
                                               float* __restrict__ XW1) {
    __shared__ __align__(16) __half sA[128 * 120];   // stride 120 halves
    __shared__ __align__(16) __half sB[112 * 72];    // stride 72 halves
    const int n0 = blockIdx.x * 64, m0 = blockIdx.y * 128;
    const int tid = threadIdx.x, lane = tid & 31, w = tid >> 5;
    const int wm = w >> 1, wn = w & 1;

    {   // A: 2 threads per row, 7 x 16B each
        int r = tid >> 1, part = tid & 1;
        const uint4* src = (const uint4*)(g_Eh + (size_t)(m0 + r) * KPAD + part * 56);
        uint4* dst = (uint4*)(sA + r * 120 + part * 56);
#pragma unroll
        for (int j = 0; j < 7; ++j) dst[j] = src[j];
    }
#pragma unroll
    for (int j = 0; j < 4; ++j) {       // B: 112x64 halves = 896 x 16B
        int idx = tid + j * 256;
        if (idx < 896) {
            int k = idx >> 3, c = idx & 7;
            *(uint4*)(sB + k * 72 + c * 8) = *(const uint4*)(g_W1h + (size_t)k * G4 + n0 + c * 8);
        }
    }
    __syncthreads();

    float acc[2][4][4];
#pragma unroll
    for (int a = 0; a < 2; ++a)
#pragma unroll
        for (int b = 0; b < 4; ++b)
#pragma unroll
            for (int i = 0; i < 4; ++i) acc[a][b][i] = 0.f;

#pragma unroll
    for (int ks = 0; ks < 7; ++ks) {
        unsigned a0[4], a1r[4], bA[4], bB[4];
        unsigned ar = smem_u32(sA) + (wm * 32 + (lane & 15)) * 240 + ks * 32 + (lane >> 4) * 16;
        ldsm_x4(a0[0], a0[1], a0[2], a0[3], ar);
        ldsm_x4(a1r[0], a1r[1], a1r[2], a1r[3], ar + 16 * 240);
        unsigned br = smem_u32(sB) + (ks * 16 + (lane & 15)) * 144 + wn * 64 + (lane >> 4) * 16;
        ldsm_x4t(bA[0], bA[1], bA[2], bA[3], br);
        ldsm_x4t(bB[0], bB[1], bB[2], bB[3], br + 32);
        mma16816(acc[0][0], a0, bA[0], bA[1]);
        mma16816(acc[0][1], a0, bA[2], bA[3]);
        mma16816(acc[0][2], a0, bB[0], bB[1]);
        mma16816(acc[0][3], a0, bB[2], bB[3]);
        mma16816(acc[1][0], a1r, bA[0], bA[1]);
        mma16816(acc[1][1], a1r, bA[2], bA[3]);
        mma16816(acc[1][2], a1r, bB[0], bB[1]);
        mma16816(acc[1][3], a1r, bB[2], bB[3]);
    }
#pragma unroll
    for (int mt = 0; mt < 2; ++mt)
#pragma unroll
        for (int nt = 0; nt < 4; ++nt)
#pragma unroll
            for (int i = 0; i < 4; ++i) {
                int rr = m0 + wm * 32 + mt * 16 + (lane >> 2) + (i >> 1) * 8;
                int cc = n0 + wn * 32 + nt * 8 + (lane & 3) * 2 + (i & 1);
                XW1[(size_t)rr * G4 + cc] = acc[mt][nt][i] + b1[cc];
            }
}

// ---------------- grid barrier (R5-verified form) ----------------
__device__ __forceinline__ void grid_barrier(unsigned phase) {
    __threadfence();
    __syncthreads();
    if (threadIdx.x == 0) {
        unsigned old = atomicAdd(&g_cnt, 1u);
        if (old == NBLK - 1) {
            g_cnt = 0;
            __threadfence();
            atomicExch(&g_gen, phase);
        } else {
            while (atomicAdd(&g_gen, 0u) < phase) __nanosleep(32);
        }
    }
    __syncthreads();
    __threadfence();
}

// stage layout (bytes): A1[128x72h]=18432 | A2=18432 | B1[64x72h]=9216 | B2[64x40h]=5120
#define O_A2 18432
#define O_B1 36864
#define O_B2 46080
#define STAGE 51200
// zb region (XW1 gate-bias slice), separate from stages: [128][36] floats
#define O_ZB (2 * STAGE)
#define DYN_TOTAL (O_ZB + 18432)

// z spill scratch (aliases stage memory; only live between trailing __syncthreads
// of the mainloop and the grid barrier)
#define ZS1_STRIDE 68
#define ZS2_STRIDE 36

__device__ __forceinline__ void issue_chunk(const __half* A1, const __half* A2,
                                            const __half* B1p, const __half* B2p,
                                            int kc, char* st, int tid) {
    unsigned b = smem_u32(st);
#pragma unroll
    for (int j = 0; j < 4; ++j) {           // A1: 128x64 halves
        int idx = tid + j * 256; int r = idx >> 3, c = idx & 7;
        cpa16(b + r * 144 + c * 16, A1 + r * UNITS + kc + c * 8);
    }
#pragma unroll
    for (int j = 0; j < 4; ++j) {           // A2
        int idx = tid + j * 256; int r = idx >> 3, c = idx & 7;
        cpa16(b + O_A2 + r * 144 + c * 16, A2 + r * UNITS + kc + c * 8);
    }
#pragma unroll
    for (int j = 0; j < 2; ++j) {           // B1: 64x64 halves
        int idx = tid + j * 256; int k = idx >> 3, c = idx & 7;
        cpa16(b + O_B1 + k * 144 + c * 16, B1p + (size_t)(kc + k) * 64 + c * 8);
    }
    {                                        // B2: 64x32 halves
        int k = tid >> 2, c = tid & 3;
        cpa16(b + O_B2 + k * 80 + c * 16, B2p + (size_t)(kc + k) * 32 + c * 8);
    }
}

__device__ __forceinline__ void compute_chunk(char* st, float acc1[2][4][4], float acc2[4][4],
                                              int wm, int wn, int w, int lane) {
    unsigned ab = smem_u32(st);
#pragma unroll
    for (int ks = 0; ks < 4; ++ks) {
        unsigned a0[4], a1r[4], a2r[4], bA[4], bB[4], b2a[4], b2b[4];
        unsigned arow = ab + (wm * 32 + (lane & 15)) * 144 + ks * 32 + (lane >> 4) * 16;
        ldsm_x4(a0[0], a0[1], a0[2], a0[3], arow);
        ldsm_x4(a1r[0], a1r[1], a1r[2], a1r[3], arow + 16 * 144);
        unsigned a2row = ab + O_A2 + (w * 16 + (lane & 15)) * 144 + ks * 32 + (lane >> 4) * 16;
        ldsm_x4(a2r[0], a2r[1], a2r[2], a2r[3], a2row);
        unsigned brow = ab + O_B1 + (ks * 16 + (lane & 15)) * 144 + wn * 64 + (lane >> 4) * 16;
        ldsm_x4t(bA[0], bA[1], bA[2], bA[3], brow);
        ldsm_x4t(bB[0], bB[1], bB[2], bB[3], brow + 32);
        unsigned b2row = ab + O_B2 + (ks * 16 + (lane & 15)) * 80 + (lane >> 4) * 16;
        ldsm_x4t(b2a[0], b2a[1], b2a[2], b2a[3], b2row);
        ldsm_x4t(b2b[0], b2b[1], b2b[2], b2b[3], b2row + 32);

        mma16816(acc1[0][0], a0, bA[0], bA[1]);
        mma16816(acc1[0][1], a0, bA[2], bA[3]);
        mma16816(acc1[0][2], a0, bB[0], bB[1]);
        mma16816(acc1[0][3], a0, bB[2], bB[3]);
        mma16816(acc1[1][0], a1r, bA[0], bA[1]);
        mma16816(acc1[1][1], a1r, bA[2], bA[3]);
        mma16816(acc1[1][2], a1r, bB[0], bB[1]);
        mma16816(acc1[1][3], a1r, bB[2], bB[3]);
        mma16816(acc2[0], a2r, b2a[0], b2a[1]);
        mma16816(acc2[1], a2r, b2a[2], b2a[3]);
        mma16816(acc2[2], a2r, b2b[0], b2b[1]);
        mma16816(acc2[3], a2r, b2b[2], b2b[3]);
    }
}

// ---------------- persistent fused 2-layer recurrence, 81 ticks ----------------
extern __shared__ __align__(16) char dynsm[];
__global__ void __launch_bounds__(256, 1) lstm_persist(const float* __restrict__ b2) {
    char* smem = dynsm;
    const int tid = threadIdx.x, lane = tid & 31, w = tid >> 5;
    const int wm = w >> 1, wn = w & 1;
    const int bx = blockIdx.x, u0 = bx * 8;
    const __half* B1p = g_B1h + (size_t)bx * UNITS * 64;
    const __half* B2p = g_B2h + (size_t)bx * UNITS * 32;
    float* zs1 = (float*)smem;                        // 128 x 64, stride 68 (aliases stages)
    float* zs2 = zs1 + 128 * ZS1_STRIDE;              // 128 x 32, stride 36
    float* zbS = (float*)(smem + O_ZB);               // 128 x 32, stride 36 (separate)
    unsigned zbA = smem_u32(zbS);

    __shared__ float sb2[32];
    if (tid < 32) sb2[tid] = b2[(size_t)(tid >> 3) * UNITS + u0 + (tid & 7)];
    __syncthreads();

    // persistent cell state in registers (thread -> row tid>>1, units hp..hp+3)
    float c1r[4] = {0.f, 0.f, 0.f, 0.f};
    float c2r[4] = {0.f, 0.f, 0.f, 0.f};

    for (int s = 0; s <= SEQ; ++s) {
        // tick s: layer1 computes h1[s] from h1[s-1]; layer2 computes h2[s-1]
        // from h1[s-1] (same A tile) and h2[s-2].
        const __half* A1 = g_h1[(s & 1) ^ 1];
        const __half* A2 = g_h2[s & 1];
        __half* h1w = g_h1[s & 1];
        __half* h2w = g_h2[(s & 1) ^ 1];

        float acc1[2][4][4]; float acc2[4][4];
#pragma unroll
        for (int a = 0; a < 2; ++a)
#pragma unroll
            for (int b = 0; b < 4; ++b)
#pragma unroll
                for (int i = 0; i < 4; ++i) acc1[a][b][i] = 0.f;
#pragma unroll
        for (int b = 0; b < 4; ++b)
#pragma unroll
            for (int i = 0; i < 4; ++i) acc2[b][i] = 0.f;

        // prologue: chunk 0 (+ XW1 gate-bias slice, same group -> done before wait0)
        issue_chunk(A1, A2, B1p, B2p, 0, smem, tid);
        if (s < SEQ) {
            const float* xw = g_XW1 + (size_t)s * BATCH * G4;
#pragma unroll
            for (int q = 0; q < 4; ++q) {
                int e = tid + q * 256;           // 0..1023: r(7b) | g(2b) | hf(1b)
                int r = e >> 3, g = (e >> 1) & 3, hf = e & 1;
                cpa16(zbA + (r * 36 + g * 8 + hf * 4) * 4,
                      xw + (size_t)r * G4 + g * UNITS + u0 + hf * 4);
            }
        }
        cp_commit();
        for (int kc = 0; kc < 16; ++kc) {
            if (kc < 15) {
                issue_chunk(A1, A2, B1p, B2p, (kc + 1) * 64, smem + ((kc + 1) & 1) * STAGE, tid);
                cp_commit();
                cp_wait1();
            } else {
                cp_wait0();
            }
            __syncthreads();
            compute_chunk(smem + (kc & 1) * STAGE, acc1, acc2, wm, wn, w, lane);
            __syncthreads();
        }

        // spill z tiles (aliases stages; dead until next tick's issue_chunk,
        // which happens only after the grid barrier below)
#pragma unroll
        for (int mt = 0; mt < 2; ++mt)
#pragma unroll
            for (int nt = 0; nt < 4; ++nt)
#pragma unroll
                for (int i = 0; i < 4; ++i) {
                    int rr = wm * 32 + mt * 16 + (lane >> 2) + (i >> 1) * 8;
                    int cc = wn * 32 + nt * 8 + (lane & 3) * 2 + (i & 1);
                    zs1[rr * ZS1_STRIDE + cc] = acc1[mt][nt][i];
                }
#pragma unroll
        for (int nt = 0; nt < 4; ++nt)
#pragma unroll
            for (int i = 0; i < 4; ++i) {
                int rr = w * 16 + (lane >> 2) + (i >> 1) * 8;
                int cc = nt * 8 + (lane & 3) * 2 + (i & 1);
                zs2[rr * ZS2_STRIDE + cc] = acc2[nt][i];
            }
        __syncthreads();

        // gates: 2 threads per batch row; zs1 cols 0..31 = h1@U1 (this block's
        // 8 units x 4 gates), cols 32..63 = h1@W2; zs2 = h2@U2; zbS = XW1 slice.
        const int r = tid >> 1;
        const int hp = (tid & 1) * 4;
        if (s < SEQ) {
#pragma unroll
            for (int j = 0; j < 4; ++j) {
                int ui = hp + j;
                int u = u0 + ui;
                float zi = zs1[r * ZS1_STRIDE + ui]      + zbS[r * 36 + ui];
                float zf = zs1[r * ZS1_STRIDE + 8 + ui]  + zbS[r * 36 + 8 + ui];
                float zg = zs1[r * ZS1_STRIDE + 16 + ui] + zbS[r * 36 + 16 + ui];
                float zo = zs1[r * ZS1_STRIDE + 24 + ui] + zbS[r * 36 + 24 + ui];
                float c = sigf(zf) * c1r[j] + sigf(zi) * tanhf(zg);
                c1r[j] = c;
                h1w[r * UNITS + u] = __float2half(sigf(zo) * tanhf(c));
            }
        }
        if (s > 0) {
#pragma unroll
            for (int j = 0; j < 4; ++j) {
                int ui = hp + j;
                int u = u0 + ui;
                float zi = zs1[r * ZS1_STRIDE + 32 + ui] + zs2[r * ZS2_STRIDE + ui]      + sb2[ui];
                float zf = zs1[r * ZS1_STRIDE + 40 + ui] + zs2[r * ZS2_STRIDE + 8 + ui]  + sb2[8 + ui];
                float zg = zs1[r * ZS1_STRIDE + 48 + ui] + zs2[r * ZS2_STRIDE + 16 + ui] + sb2[16 + ui];
                float zo = zs1[r * ZS1_STRIDE + 56 + ui] + zs2[r * ZS2_STRIDE + 24 + ui] + sb2[24 + ui];
                float c = sigf(zf) * c2r[j] + sigf(zi) * tanhf(zg);
                c2r[j] = c;
                h2w[r * UNITS + u] = __float2half(sigf(zo) * tanhf(c));
            }
        }
        grid_barrier((unsigned)(s + 1));
    }
}

// ---------------- final dense + sigmoid ----------------
__global__ void final_kernel(const float* __restrict__ Wfc, const float* __restrict__ bfc,
                             float* __restrict__ out) {
    const int b = blockIdx.x;
    const int tid = threadIdx.x;   // 128
    const __half* h2 = g_h2[1];    // h2[79] written at tick 80 -> buffer (80&1)^1 = 1
    float s = 0.f;
#pragma unroll
    for (int k = 0; k < 8; ++k) {
        int u = tid + k * 128;
        s += __half2float(h2[b * UNITS + u]) * Wfc[u];
    }
#pragma unroll
    for (int o = 16; o > 0; o >>= 1) s += __shfl_down_sync(0xffffffffu, s, o);
    __shared__ float ws[4];
    if ((tid & 31) == 0) ws[tid >> 5] = s;
    __syncthreads();
    if (tid == 0) {
        float tot = ws[0] + ws[1] + ws[2] + ws[3] + bfc[0];
        out[b] = 1.0f / (1.0f + expf(-tot));
    }
}

// ---------------- launcher ----------------
extern "C" void kernel_launch(void* const* d_in, const int* in_sizes, int n_in,
                              void* d_out, int out_size) {
    const int*   x   = (const int*)d_in[0];
    const float* emb = (const float*)d_in[1];
    const float* W1  = (const float*)d_in[2];
    const float* U1  = (const float*)d_in[3];
    const float* b1  = (const float*)d_in[4];
    const float* W2  = (const float*)d_in[5];
    const float* U2  = (const float*)d_in[6];
    const float* b2  = (const float*)d_in[7];
    const float* Wfc = (const float*)d_in[8];
    const float* bfc = (const float*)d_in[9];
    float* out = (float*)d_out;

    float* XW1p;
    cudaGetSymbolAddress((void**)&XW1p, g_XW1);

    cudaFuncSetAttribute((const void*)lstm_persist,
                         cudaFuncAttributeMaxDynamicSharedMemorySize, DYN_TOTAL);

    init_kernel<<<512, 256>>>();
    gather_emb<<<SEQ * BATCH, 128>>>(x, emb);
    pack_w1<<<KPAD, 256>>>(W1);
    pack_b<<<2048, 256>>>(U1, W2, U2);
    xw1_mma<<<dim3(G4 / 64, SEQ * BATCH / 128), 256>>>(b1, XW1p);
    lstm_persist<<<NBLK, 256, DYN_TOTAL>>>(b2);
    final_kernel<<<BATCH, 128>>>(Wfc, bfc, out);
}

// round 12
// speedup vs baseline: 1.3562x; 1.0092x over previous
#include <cuda_runtime.h>
#include <cuda_fp16.h>
#include <math.h>
#include <stdint.h>

#define BATCH 128
#define SEQ   80
#define EMB_D 100
#define UNITS 1024
#define G4    4096
#define NBLK  128
#define KPAD  112

// ---------------- device scratch ----------------
__device__ __align__(16) float  g_XW1[(size_t)SEQ * BATCH * G4];
__device__ __align__(16) __half g_Eh[(size_t)SEQ * BATCH * KPAD];   // gathered emb, K padded
__device__ __align__(16) __half g_W1h[(size_t)KPAD * G4];
__device__ __align__(16) __half g_B1h[(size_t)NBLK * UNITS * 64];   // [bx][k][ U1(32) | W2(32) ]
__device__ __align__(16) __half g_B2h[(size_t)NBLK * UNITS * 32];   // [bx][k][ U2(32) ]
__device__ __align__(16) __half g_h1[2][BATCH * UNITS];
__device__ __align__(16) __half g_h2[2][BATCH * UNITS];
__device__ unsigned g_cnt;
__device__ unsigned g_gen;

__device__ __forceinline__ float sigf(float x) { return 1.0f / (1.0f + expf(-x)); }

// ---------------- PTX helpers ----------------
__device__ __forceinline__ unsigned smem_u32(const void* p) {
    return (unsigned)__cvta_generic_to_shared(p);
}
__device__ __forceinline__ void ldsm_x4(unsigned& r0, unsigned& r1, unsigned& r2, unsigned& r3,
                                        unsigned addr) {
    asm volatile("ldmatrix.sync.aligned.m8n8.x4.shared.b16 {%0,%1,%2,%3}, [%4];\n"
                 : "=r"(r0), "=r"(r1), "=r"(r2), "=r"(r3) : "r"(addr));
}
__device__ __forceinline__ void ldsm_x4t(unsigned& r0, unsigned& r1, unsigned& r2, unsigned& r3,
                                         unsigned addr) {
    asm volatile("ldmatrix.sync.aligned.m8n8.x4.trans.shared.b16 {%0,%1,%2,%3}, [%4];\n"
                 : "=r"(r0), "=r"(r1), "=r"(r2), "=r"(r3) : "r"(addr));
}
__device__ __forceinline__ void mma16816(float* d, const unsigned* a, unsigned b0, unsigned b1) {
    asm volatile(
        "mma.sync.aligned.m16n8k16.row.col.f32.f16.f16.f32 "
        "{%0,%1,%2,%3},{%4,%5,%6,%7},{%8,%9},{%0,%1,%2,%3};\n"
        : "+f"(d[0]), "+f"(d[1]), "+f"(d[2]), "+f"(d[3])
        : "r"(a[0]), "r"(a[1]), "r"(a[2]), "r"(a[3]), "r"(b0), "r"(b1));
}
__device__ __forceinline__ void cpa16(unsigned dst, const void* src) {
    asm volatile("cp.async.cg.shared.global [%0], [%1], 16;\n" :: "r"(dst), "l"(src));
}
__device__ __forceinline__ void cp_commit() { asm volatile("cp.async.commit_group;\n"); }
__device__ __forceinline__ void cp_wait1() { asm volatile("cp.async.wait_group 1;\n"); }
__device__ __forceinline__ void cp_wait0() { asm volatile("cp.async.wait_group 0;\n"); }

// ---------------- init (deterministic per replay) ----------------
__global__ void init_kernel() {
    int i = blockIdx.x * blockDim.x + threadIdx.x;
    if (i == 0) { g_cnt = 0; g_gen = 0; }
    if (i < BATCH * UNITS) {
        g_h1[0][i] = __float2half(0.f); g_h1[1][i] = __float2half(0.f);
        g_h2[0][i] = __float2half(0.f); g_h2[1][i] = __float2half(0.f);
    }
}

// ---------------- gather embedding rows -> fp16 [m][112] ----------------
__global__ void gather_emb(const int* __restrict__ x, const float* __restrict__ emb) {
    int m = blockIdx.x;                 // m = t*128 + b
    int tid = threadIdx.x;              // 128
    int b = m & 127, t = m >> 7;
    int tok = x[b * SEQ + t];
    if (tid < KPAD)
        g_Eh[(size_t)m * KPAD + tid] =
            __float2half(tid < EMB_D ? emb[(size_t)tok * EMB_D + tid] : 0.f);
}

__global__ void pack_w1(const float* __restrict__ W1) {
    int k = blockIdx.x;                 // 0..111
    for (int n = threadIdx.x; n < G4; n += blockDim.x)
        g_W1h[(size_t)k * G4 + n] = __float2half(k < EMB_D ? W1[(size_t)k * G4 + n] : 0.f);
}

// ---------------- pack recurrent weights into per-block fp16 slices ----------------
__global__ void pack_b(const float* __restrict__ U1, const float* __restrict__ W2,
                       const float* __restrict__ U2) {
    const size_t tot1 = (size_t)NBLK * UNITS * 64;
    for (size_t i = blockIdx.x * (size_t)blockDim.x + threadIdx.x; i < tot1;
         i += (size_t)gridDim.x * blockDim.x) {
        int c  = (int)(i & 63);
        int k  = (int)((i >> 6) & 1023);
        int bx = (int)(i >> 16);
        int cc = c & 31;
        size_t src = (size_t)k * G4 + (cc >> 3) * UNITS + bx * 8 + (cc & 7);
        g_B1h[i] = __float2half(c < 32 ? U1[src] : W2[src]);
    }
    const size_t tot2 = (size_t)NBLK * UNITS * 32;
    for (size_t i = blockIdx.x * (size_t)blockDim.x + threadIdx.x; i < tot2;
         i += (size_t)gridDim.x * blockDim.x) {
        int c  = (int)(i & 31);
        int k  = (int)((i >> 5) & 1023);
        int bx = (int)(i >> 15);
        size_t src = (size_t)k * G4 + (c >> 3) * UNITS + bx * 8 + (c & 7);
        g_B2h[i] = __float2half(U2[src]);
    }
}

// ---------------- XW1 = Eh @ W1h + b1 (tensor cores, K=112) ----------------
__global__ void __launch_bounds__(256) xw1_mma(const float* __restrict__ b1,
                                               float* __restrict__ XW1) {
    __shared__ __align__(16) __half sA[128 * 120];   // stride 120 halves
    __shared__ __align__(16) __half sB[112 * 72];    // stride 72 halves
    const int n0 = blockIdx.x * 64, m0 = blockIdx.y * 128;
    const int tid = threadIdx.x, lane = tid & 31, w = tid >> 5;
    const int wm = w >> 1, wn = w & 1;

    {   // A: 2 threads per row, 7 x 16B each
        int r = tid >> 1, part = tid & 1;
        const uint4* src = (const uint4*)(g_Eh + (size_t)(m0 + r) * KPAD + part * 56);
        uint4* dst = (uint4*)(sA + r * 120 + part * 56);
#pragma unroll
        for (int j = 0; j < 7; ++j) dst[j] = src[j];
    }
#pragma unroll
    for (int j = 0; j < 4; ++j) {       // B: 112x64 halves = 896 x 16B
        int idx = tid + j * 256;
        if (idx < 896) {
            int k = idx >> 3, c = idx & 7;
            *(uint4*)(sB + k * 72 + c * 8) = *(const uint4*)(g_W1h + (size_t)k * G4 + n0 + c * 8);
        }
    }
    __syncthreads();

    float acc[2][4][4];
#pragma unroll
    for (int a = 0; a < 2; ++a)
#pragma unroll
        for (int b = 0; b < 4; ++b)
#pragma unroll
            for (int i = 0; i < 4; ++i) acc[a][b][i] = 0.f;

#pragma unroll
    for (int ks = 0; ks < 7; ++ks) {
        unsigned a0[4], a1r[4], bA[4], bB[4];
        unsigned ar = smem_u32(sA) + (wm * 32 + (lane & 15)) * 240 + ks * 32 + (lane >> 4) * 16;
        ldsm_x4(a0[0], a0[1], a0[2], a0[3], ar);
        ldsm_x4(a1r[0], a1r[1], a1r[2], a1r[3], ar + 16 * 240);
        unsigned br = smem_u32(sB) + (ks * 16 + (lane & 15)) * 144 + wn * 64 + (lane >> 4) * 16;
        ldsm_x4t(bA[0], bA[1], bA[2], bA[3], br);
        ldsm_x4t(bB[0], bB[1], bB[2], bB[3], br + 32);
        mma16816(acc[0][0], a0, bA[0], bA[1]);
        mma16816(acc[0][1], a0, bA[2], bA[3]);
        mma16816(acc[0][2], a0, bB[0], bB[1]);
        mma16816(acc[0][3], a0, bB[2], bB[3]);
        mma16816(acc[1][0], a1r, bA[0], bA[1]);
        mma16816(acc[1][1], a1r, bA[2], bA[3]);
        mma16816(acc[1][2], a1r, bB[0], bB[1]);
        mma16816(acc[1][3], a1r, bB[2], bB[3]);
    }
#pragma unroll
    for (int mt = 0; mt < 2; ++mt)
#pragma unroll
        for (int nt = 0; nt < 4; ++nt)
#pragma unroll
            for (int i = 0; i < 4; ++i) {
                int rr = m0 + wm * 32 + mt * 16 + (lane >> 2) + (i >> 1) * 8;
                int cc = n0 + wn * 32 + nt * 8 + (lane & 3) * 2 + (i & 1);
                XW1[(size_t)rr * G4 + cc] = acc[mt][nt][i] + b1[cc];
            }
}

// ---------------- grid barrier (R5-verified form) ----------------
__device__ __forceinline__ void grid_barrier(unsigned phase) {
    __threadfence();
    __syncthreads();
    if (threadIdx.x == 0) {
        unsigned old = atomicAdd(&g_cnt, 1u);
        if (old == NBLK - 1) {
            g_cnt = 0;
            __threadfence();
            atomicExch(&g_gen, phase);
        } else {
            while (atomicAdd(&g_gen, 0u) < phase) __nanosleep(32);
        }
    }
    __syncthreads();
    __threadfence();
}

// stage layout (bytes): A1[128x72h]=18432 | A2=18432 | B1[64x72h]=9216 | B2[64x40h]=5120
#define O_A2 18432
#define O_B1 36864
#define O_B2 46080
#define STAGE 51200
// zb region (XW1 gate-bias slice), separate from stages: [128][36] floats
#define O_ZB (2 * STAGE)
#define DYN_TOTAL (O_ZB + 18432)

// z spill scratch (aliases stage memory; only live between trailing __syncthreads
// of the mainloop and the grid barrier)
#define ZS1_STRIDE 68
#define ZS2_STRIDE 36

__device__ __forceinline__ void issue_chunk(const __half* A1, const __half* A2,
                                            const __half* B1p, const __half* B2p,
                                            int kc, char* st, int tid) {
    unsigned b = smem_u32(st);
#pragma unroll
    for (int j = 0; j < 4; ++j) {           // A1: 128x64 halves
        int idx = tid + j * 256; int r = idx >> 3, c = idx & 7;
        cpa16(b + r * 144 + c * 16, A1 + r * UNITS + kc + c * 8);
    }
#pragma unroll
    for (int j = 0; j < 4; ++j) {           // A2
        int idx = tid + j * 256; int r = idx >> 3, c = idx & 7;
        cpa16(b + O_A2 + r * 144 + c * 16, A2 + r * UNITS + kc + c * 8);
    }
#pragma unroll
    for (int j = 0; j < 2; ++j) {           // B1: 64x64 halves
        int idx = tid + j * 256; int k = idx >> 3, c = idx & 7;
        cpa16(b + O_B1 + k * 144 + c * 16, B1p + (size_t)(kc + k) * 64 + c * 8);
    }
    {                                        // B2: 64x32 halves
        int k = tid >> 2, c = tid & 3;
        cpa16(b + O_B2 + k * 80 + c * 16, B2p + (size_t)(kc + k) * 32 + c * 8);
    }
}

__device__ __forceinline__ void compute_chunk(char* st, float acc1[2][4][4], float acc2[4][4],
                                              int wm, int wn, int w, int lane) {
    unsigned ab = smem_u32(st);
#pragma unroll
    for (int ks = 0; ks < 4; ++ks) {
        unsigned a0[4], a1r[4], a2r[4], bA[4], bB[4], b2a[4], b2b[4];
        unsigned arow = ab + (wm * 32 + (lane & 15)) * 144 + ks * 32 + (lane >> 4) * 16;
        ldsm_x4(a0[0], a0[1], a0[2], a0[3], arow);
        ldsm_x4(a1r[0], a1r[1], a1r[2], a1r[3], arow + 16 * 144);
        unsigned a2row = ab + O_A2 + (w * 16 + (lane & 15)) * 144 + ks * 32 + (lane >> 4) * 16;
        ldsm_x4(a2r[0], a2r[1], a2r[2], a2r[3], a2row);
        unsigned brow = ab + O_B1 + (ks * 16 + (lane & 15)) * 144 + wn * 64 + (lane >> 4) * 16;
        ldsm_x4t(bA[0], bA[1], bA[2], bA[3], brow);
        ldsm_x4t(bB[0], bB[1], bB[2], bB[3], brow + 32);
        unsigned b2row = ab + O_B2 + (ks * 16 + (lane & 15)) * 80 + (lane >> 4) * 16;
        ldsm_x4t(b2a[0], b2a[1], b2a[2], b2a[3], b2row);
        ldsm_x4t(b2b[0], b2b[1], b2b[2], b2b[3], b2row + 32);

        mma16816(acc1[0][0], a0, bA[0], bA[1]);
        mma16816(acc1[0][1], a0, bA[2], bA[3]);
        mma16816(acc1[0][2], a0, bB[0], bB[1]);
        mma16816(acc1[0][3], a0, bB[2], bB[3]);
        mma16816(acc1[1][0], a1r, bA[0], bA[1]);
        mma16816(acc1[1][1], a1r, bA[2], bA[3]);
        mma16816(acc1[1][2], a1r, bB[0], bB[1]);
        mma16816(acc1[1][3], a1r, bB[2], bB[3]);
        mma16816(acc2[0], a2r, b2a[0], b2a[1]);
        mma16816(acc2[1], a2r, b2a[2], b2a[3]);
        mma16816(acc2[2], a2r, b2b[0], b2b[1]);
        mma16816(acc2[3], a2r, b2b[2], b2b[3]);
    }
}

// ---------------- persistent fused 2-layer recurrence, 81 ticks ----------------
extern __shared__ __align__(16) char dynsm[];
__global__ void __launch_bounds__(256, 1) lstm_persist(const float* __restrict__ b2) {
    char* smem = dynsm;
    const int tid = threadIdx.x, lane = tid & 31, w = tid >> 5;
    const int wm = w >> 1, wn = w & 1;
    const int bx = blockIdx.x, u0 = bx * 8;
    const int koff = bx & 15;                 // per-block K-chunk rotation (L2 de-hotspot)
    const __half* B1p = g_B1h + (size_t)bx * UNITS * 64;
    const __half* B2p = g_B2h + (size_t)bx * UNITS * 32;
    float* zs1 = (float*)smem;                        // 128 x 64, stride 68 (aliases stages)
    float* zs2 = zs1 + 128 * ZS1_STRIDE;              // 128 x 32, stride 36
    float* zbS = (float*)(smem + O_ZB);               // 128 x 32, stride 36 (separate)
    unsigned zbA = smem_u32(zbS);

    __shared__ float sb2[32];
    if (tid < 32) sb2[tid] = b2[(size_t)(tid >> 3) * UNITS + u0 + (tid & 7)];
    __syncthreads();

    // persistent cell state in registers (thread -> row tid>>1, units hp..hp+3)
    float c1r[4] = {0.f, 0.f, 0.f, 0.f};
    float c2r[4] = {0.f, 0.f, 0.f, 0.f};

    for (int s = 0; s <= SEQ; ++s) {
        // tick s: layer1 computes h1[s] from h1[s-1]; layer2 computes h2[s-1]
        // from h1[s-1] (same A tile) and h2[s-2].
        const __half* A1 = g_h1[(s & 1) ^ 1];
        const __half* A2 = g_h2[s & 1];
        __half* h1w = g_h1[s & 1];
        __half* h2w = g_h2[(s & 1) ^ 1];

        float acc1[2][4][4]; float acc2[4][4];
#pragma unroll
        for (int a = 0; a < 2; ++a)
#pragma unroll
            for (int b = 0; b < 4; ++b)
#pragma unroll
                for (int i = 0; i < 4; ++i) acc1[a][b][i] = 0.f;
#pragma unroll
        for (int b = 0; b < 4; ++b)
#pragma unroll
            for (int i = 0; i < 4; ++i) acc2[b][i] = 0.f;

        // prologue: chunk 0 (+ XW1 gate-bias slice, same group -> done before wait0)
        issue_chunk(A1, A2, B1p, B2p, koff * 64, smem, tid);
        if (s < SEQ) {
            const float* xw = g_XW1 + (size_t)s * BATCH * G4;
#pragma unroll
            for (int q = 0; q < 4; ++q) {
                int e = tid + q * 256;           // 0..1023: r(7b) | g(2b) | hf(1b)
                int r = e >> 3, g = (e >> 1) & 3, hf = e & 1;
                cpa16(zbA + (r * 36 + g * 8 + hf * 4) * 4,
                      xw + (size_t)r * G4 + g * UNITS + u0 + hf * 4);
            }
        }
        cp_commit();
        for (int kc = 0; kc < 16; ++kc) {
            if (kc < 15) {
                issue_chunk(A1, A2, B1p, B2p, ((kc + 1 + koff) & 15) * 64,
                            smem + ((kc + 1) & 1) * STAGE, tid);
                cp_commit();
                cp_wait1();
            } else {
                cp_wait0();
            }
            __syncthreads();
            compute_chunk(smem + (kc & 1) * STAGE, acc1, acc2, wm, wn, w, lane);
            __syncthreads();
        }

        // spill z tiles (aliases stages; dead until next tick's issue_chunk,
        // which happens only after the grid barrier below)
#pragma unroll
        for (int mt = 0; mt < 2; ++mt)
#pragma unroll
            for (int nt = 0; nt < 4; ++nt)
#pragma unroll
                for (int i = 0; i < 4; ++i) {
                    int rr = wm * 32 + mt * 16 + (lane >> 2) + (i >> 1) * 8;
                    int cc = wn * 32 + nt * 8 + (lane & 3) * 2 + (i & 1);
                    zs1[rr * ZS1_STRIDE + cc] = acc1[mt][nt][i];
                }
#pragma unroll
        for (int nt = 0; nt < 4; ++nt)
#pragma unroll
            for (int i = 0; i < 4; ++i) {
                int rr = w * 16 + (lane >> 2) + (i >> 1) * 8;
                int cc = nt * 8 + (lane & 3) * 2 + (i & 1);
                zs2[rr * ZS2_STRIDE + cc] = acc2[nt][i];
            }
        __syncthreads();

        // gates: 2 threads per batch row; zs1 cols 0..31 = h1@U1 (this block's
        // 8 units x 4 gates), cols 32..63 = h1@W2; zs2 = h2@U2; zbS = XW1 slice.
        const int r = tid >> 1;
        const int hp = (tid & 1) * 4;
        if (s < SEQ) {
#pragma unroll
            for (int j = 0; j < 4; ++j) {
                int ui = hp + j;
                int u = u0 + ui;
                float zi = zs1[r * ZS1_STRIDE + ui]      + zbS[r * 36 + ui];
                float zf = zs1[r * ZS1_STRIDE + 8 + ui]  + zbS[r * 36 + 8 + ui];
                float zg = zs1[r * ZS1_STRIDE + 16 + ui] + zbS[r * 36 + 16 + ui];
                float zo = zs1[r * ZS1_STRIDE + 24 + ui] + zbS[r * 36 + 24 + ui];
                float c = sigf(zf) * c1r[j] + sigf(zi) * tanhf(zg);
                c1r[j] = c;
                h1w[r * UNITS + u] = __float2half(sigf(zo) * tanhf(c));
            }
        }
        if (s > 0) {
#pragma unroll
            for (int j = 0; j < 4; ++j) {
                int ui = hp + j;
                int u = u0 + ui;
                float zi = zs1[r * ZS1_STRIDE + 32 + ui] + zs2[r * ZS2_STRIDE + ui]      + sb2[ui];
                float zf = zs1[r * ZS1_STRIDE + 40 + ui] + zs2[r * ZS2_STRIDE + 8 + ui]  + sb2[8 + ui];
                float zg = zs1[r * ZS1_STRIDE + 48 + ui] + zs2[r * ZS2_STRIDE + 16 + ui] + sb2[16 + ui];
                float zo = zs1[r * ZS1_STRIDE + 56 + ui] + zs2[r * ZS2_STRIDE + 24 + ui] + sb2[24 + ui];
                float c = sigf(zf) * c2r[j] + sigf(zi) * tanhf(zg);
                c2r[j] = c;
                h2w[r * UNITS + u] = __float2half(sigf(zo) * tanhf(c));
            }
        }
        grid_barrier((unsigned)(s + 1));
    }
}

// ---------------- final dense + sigmoid ----------------
__global__ void final_kernel(const float* __restrict__ Wfc, const float* __restrict__ bfc,
                             float* __restrict__ out) {
    const int b = blockIdx.x;
    const int tid = threadIdx.x;   // 128
    const __half* h2 = g_h2[1];    // h2[79] written at tick 80 -> buffer (80&1)^1 = 1
    float s = 0.f;
#pragma unroll
    for (int k = 0; k < 8; ++k) {
        int u = tid + k * 128;
        s += __half2float(h2[b * UNITS + u]) * Wfc[u];
    }
#pragma unroll
    for (int o = 16; o > 0; o >>= 1) s += __shfl_down_sync(0xffffffffu, s, o);
    __shared__ float ws[4];
    if ((tid & 31) == 0) ws[tid >> 5] = s;
    __syncthreads();
    if (tid == 0) {
        float tot = ws[0] + ws[1] + ws[2] + ws[3] + bfc[0];
        out[b] = 1.0f / (1.0f + expf(-tot));
    }
}

// ---------------- launcher ----------------
extern "C" void kernel_launch(void* const* d_in, const int* in_sizes, int n_in,
                              void* d_out, int out_size) {
    const int*   x   = (const int*)d_in[0];
    const float* emb = (const float*)d_in[1];
    const float* W1  = (const float*)d_in[2];
    const float* U1  = (const float*)d_in[3];
    const float* b1  = (const float*)d_in[4];
    const float* W2  = (const float*)d_in[5];
    const float* U2  = (const float*)d_in[6];
    const float* b2  = (const float*)d_in[7];
    const float* Wfc = (const float*)d_in[8];
    const float* bfc = (const float*)d_in[9];
    float* out = (float*)d_out;

    float* XW1p;
    cudaGetSymbolAddress((void**)&XW1p, g_XW1);

    cudaFuncSetAttribute((const void*)lstm_persist,
                         cudaFuncAttributeMaxDynamicSharedMemorySize, DYN_TOTAL);

    init_kernel<<<512, 256>>>();
    gather_emb<<<SEQ * BATCH, 128>>>(x, emb);
    pack_w1<<<KPAD, 256>>>(W1);
    pack_b<<<2048, 256>>>(U1, W2, U2);
    xw1_mma<<<dim3(G4 / 64, SEQ * BATCH / 128), 256>>>(b1, XW1p);
    lstm_persist<<<NBLK, 256, DYN_TOTAL>>>(b2);
    final_kernel<<<BATCH, 128>>>(Wfc, bfc, out);
}